// round 7
// baseline (speedup 1.0000x reference)
#include <cuda_runtime.h>

// SKA: out[b, g*8+cw, h, w] = sum_{i,j} x[b, g*8+cw, h+i-1, w+j-1] * w[b, cw, i*3+j, h, w]
// x: (8,64,128,128) f32, w: (8,8,9,128,128) f32, out: (8,64,128,128) f32
//
// R6: cut L1tex wavefront traffic. Halo columns come from neighbor lanes via
// warp shuffle (warp spans the full 128-wide row) instead of strided scalar
// LDGs (which cost 4 wavefronts for 128B useful). Per g-iter load wavefronts:
// 20 -> 12. Weights stay in registers (R4 showed smem/LDS gives the savings
// back on the same MIO path). Layout = R5: 128-thread blocks, single wave.

#define SKA_H 128
#define SKA_W 128
#define SKA_C 64
#define SKA_CW 8
#define SKA_HW (SKA_H * SKA_W)

__global__ __launch_bounds__(128, 8)
void SKA_44830868635847_kernel(const float* __restrict__ x,
                               const float* __restrict__ wgt,
                               float* __restrict__ out) {
    const int tid  = threadIdx.x;
    const int lane = tid & 31;
    const int w0   = lane << 2;    // 0,4,...,124 (warp spans the full row)
    const int wid  = tid >> 5;     // 0..3
    const int h    = blockIdx.x;   // 0..127
    const int b    = blockIdx.y;   // 0..7
    const unsigned FULL = 0xFFFFFFFFu;

    const float* xb = x + (long)(b * SKA_C) * SKA_HW;
    float* ob = out + (long)(b * SKA_C) * SKA_HW;

    #pragma unroll 1
    for (int half = 0; half < 2; half++) {
        const int cw = wid + half * 4;   // weight channel for this pass

        // 9 per-position weight vectors for (b, cw, h, w0..w0+3), in registers,
        // reused across all 8 group channels.
        float4 wv[9];
        const float* wp = wgt + ((long)(b * SKA_CW + cw) * 9 * SKA_H + h) * SKA_W + w0;
        #pragma unroll
        for (int k = 0; k < 9; k++) {
            wv[k] = *reinterpret_cast<const float4*>(wp + (long)k * SKA_HW);
        }

        #pragma unroll
        for (int g = 0; g < 8; g++) {
            const int c = g * SKA_CW + cw;
            const float* xc = xb + (long)c * SKA_HW;

            float acc0 = 0.f, acc1 = 0.f, acc2 = 0.f, acc3 = 0.f;

            #pragma unroll
            for (int i = 0; i < 3; i++) {
                const int hh = h + i - 1;
                float r0, r1, r2, r3, r4, r5;
                if (hh < 0 || hh >= SKA_H) {           // warp-uniform branch
                    r0 = r1 = r2 = r3 = r4 = r5 = 0.f;
                } else {
                    const float4 m =
                        *reinterpret_cast<const float4*>(xc + hh * SKA_W + w0);
                    r1 = m.x; r2 = m.y; r3 = m.z; r4 = m.w;
                    // halo columns from neighbor lanes (no extra LDG)
                    r0 = __shfl_up_sync(FULL, m.w, 1);
                    r5 = __shfl_down_sync(FULL, m.x, 1);
                    if (lane == 0)  r0 = 0.f;          // w == 0 border
                    if (lane == 31) r5 = 0.f;          // w == 127 border
                }
                {
                    const float4 wk = wv[i * 3 + 0];   // j=0
                    acc0 = fmaf(wk.x, r0, acc0);
                    acc1 = fmaf(wk.y, r1, acc1);
                    acc2 = fmaf(wk.z, r2, acc2);
                    acc3 = fmaf(wk.w, r3, acc3);
                }
                {
                    const float4 wk = wv[i * 3 + 1];   // j=1
                    acc0 = fmaf(wk.x, r1, acc0);
                    acc1 = fmaf(wk.y, r2, acc1);
                    acc2 = fmaf(wk.z, r3, acc2);
                    acc3 = fmaf(wk.w, r4, acc3);
                }
                {
                    const float4 wk = wv[i * 3 + 2];   // j=2
                    acc0 = fmaf(wk.x, r2, acc0);
                    acc1 = fmaf(wk.y, r3, acc1);
                    acc2 = fmaf(wk.z, r4, acc2);
                    acc3 = fmaf(wk.w, r5, acc3);
                }
            }

            float4 o;
            o.x = acc0; o.y = acc1; o.z = acc2; o.w = acc3;
            *reinterpret_cast<float4*>(ob + (long)c * SKA_HW + h * SKA_W + w0) = o;
        }
    }
}

extern "C" void kernel_launch(void* const* d_in, const int* in_sizes, int n_in,
                              void* d_out, int out_size) {
    const float* x = (const float*)d_in[0];
    const float* w = (const float*)d_in[1];
    float* out = (float*)d_out;
    (void)in_sizes; (void)n_in; (void)out_size;

    dim3 grid(SKA_H, 8);   // (h, b): 1024 blocks
    dim3 block(128);       // 4 warps; each warp covers cw=wid and wid+4
    SKA_44830868635847_kernel<<<grid, block>>>(x, w, out);
}

// round 9
// speedup vs baseline: 1.2620x; 1.2620x over previous
#include <cuda_runtime.h>

// SKA: out[b, g*8+cw, h, w] = sum_{i,j} x[b, g*8+cw, h+i-1, w+j-1] * w[b, cw, i*3+j, h, w]
// x: (8,64,128,128) f32, w: (8,8,9,128,128) f32, out: (8,64,128,128) f32
//
// R7: MLP fix. Evidence: ~3 TB/s at ~300ns latency => only ~1.7 cache lines in
// flight per warp; the old 64-reg cap serialized the load stream. Restructure:
// i-outer / g-inner with 4 channels per chunk so each i-step batches
// 3 weight + 4 x-row float4 loads (+8 independent scalar halos) in flight,
// and raise the reg cap to 85 (__launch_bounds__(128,6)) so the batch lives
// in registers. Occupancy drop is irrelevant (proven R3-R6).

#define SKA_H 128
#define SKA_W 128
#define SKA_C 64
#define SKA_CW 8
#define SKA_HW (SKA_H * SKA_W)

__global__ __launch_bounds__(128, 6)
void SKA_44830868635847_kernel(const float* __restrict__ x,
                               const float* __restrict__ wgt,
                               float* __restrict__ out) {
    const int tid  = threadIdx.x;
    const int lane = tid & 31;
    const int w0   = lane << 2;    // 0,4,...,124
    const int wid  = tid >> 5;     // 0..3
    const int h    = blockIdx.x;   // 0..127
    const int b    = blockIdx.y;   // 0..7

    const float* xb = x + (long)(b * SKA_C) * SKA_HW;
    float* ob = out + (long)(b * SKA_C) * SKA_HW;

    #pragma unroll 1
    for (int half = 0; half < 2; half++) {
        const int cw = wid + half * 4;
        const float* wp =
            wgt + ((long)(b * SKA_CW + cw) * 9 * SKA_H + h) * SKA_W + w0;

        #pragma unroll 1
        for (int chunk = 0; chunk < 2; chunk++) {
            float4 acc[4];
            #pragma unroll
            for (int q = 0; q < 4; q++) acc[q] = make_float4(0.f, 0.f, 0.f, 0.f);

            #pragma unroll
            for (int i = 0; i < 3; i++) {
                const int hh = h + i - 1;

                // batch: 3 weight vectors + 4 x-rows (+halos), all independent
                const float4 wk0 = *reinterpret_cast<const float4*>(wp + (long)(i * 3 + 0) * SKA_HW);
                const float4 wk1 = *reinterpret_cast<const float4*>(wp + (long)(i * 3 + 1) * SKA_HW);
                const float4 wk2 = *reinterpret_cast<const float4*>(wp + (long)(i * 3 + 2) * SKA_HW);

                float r[4][6];
                if (hh >= 0 && hh < SKA_H) {           // warp-uniform branch
                    #pragma unroll
                    for (int q = 0; q < 4; q++) {
                        const int c = (chunk * 4 + q) * SKA_CW + cw;
                        const float* row = xb + (long)c * SKA_HW + hh * SKA_W + w0;
                        const float4 m = *reinterpret_cast<const float4*>(row);
                        r[q][1] = m.x; r[q][2] = m.y; r[q][3] = m.z; r[q][4] = m.w;
                        r[q][0] = (w0 == 0)         ? 0.f : row[-1];
                        r[q][5] = (w0 + 4 >= SKA_W) ? 0.f : row[4];
                    }
                } else {
                    #pragma unroll
                    for (int q = 0; q < 4; q++)
                        #pragma unroll
                        for (int t = 0; t < 6; t++) r[q][t] = 0.f;
                }

                #pragma unroll
                for (int q = 0; q < 4; q++) {
                    acc[q].x = fmaf(wk0.x, r[q][0], acc[q].x);
                    acc[q].y = fmaf(wk0.y, r[q][1], acc[q].y);
                    acc[q].z = fmaf(wk0.z, r[q][2], acc[q].z);
                    acc[q].w = fmaf(wk0.w, r[q][3], acc[q].w);

                    acc[q].x = fmaf(wk1.x, r[q][1], acc[q].x);
                    acc[q].y = fmaf(wk1.y, r[q][2], acc[q].y);
                    acc[q].z = fmaf(wk1.z, r[q][3], acc[q].z);
                    acc[q].w = fmaf(wk1.w, r[q][4], acc[q].w);

                    acc[q].x = fmaf(wk2.x, r[q][2], acc[q].x);
                    acc[q].y = fmaf(wk2.y, r[q][3], acc[q].y);
                    acc[q].z = fmaf(wk2.z, r[q][4], acc[q].z);
                    acc[q].w = fmaf(wk2.w, r[q][5], acc[q].w);
                }
            }

            #pragma unroll
            for (int q = 0; q < 4; q++) {
                const int c = (chunk * 4 + q) * SKA_CW + cw;
                *reinterpret_cast<float4*>(ob + (long)c * SKA_HW + h * SKA_W + w0) = acc[q];
            }
        }
    }
}

extern "C" void kernel_launch(void* const* d_in, const int* in_sizes, int n_in,
                              void* d_out, int out_size) {
    const float* x = (const float*)d_in[0];
    const float* w = (const float*)d_in[1];
    float* out = (float*)d_out;
    (void)in_sizes; (void)n_in; (void)out_size;

    dim3 grid(SKA_H, 8);   // (h, b)
    dim3 block(128);       // 4 warps; warp covers cw=wid and wid+4
    SKA_44830868635847_kernel<<<grid, block>>>(x, w, out);
}

// round 13
// speedup vs baseline: 1.3798x; 1.0934x over previous
#include <cuda_runtime.h>

// SKA: out[b, g*8+cw, h, w] = sum_{i,j} x[b, g*8+cw, h+i-1, w+j-1] * w[b, cw, i*3+j, h, w]
// x: (8,64,128,128) f32, w: (8,8,9,128,128) f32, out: (8,64,128,128) f32
//
// R9 = R5 body (best: 25.9us kernel) + L2 software prefetch.
// Finding: every variant moves the same ~77MB of DRAM traffic and
// dur = 77MB / achieved-BW, with DRAM only ~37% busy -> bound by sparse,
// serialized DRAM misses (most loads L2-hit across graph replays).
// prefetch.global.L2 has no destination register, so the whole half's
// x-row address stream is issued up front at zero register cost, queueing
// the misses early and raising DRAM-level parallelism.

#define SKA_H 128
#define SKA_W 128
#define SKA_C 64
#define SKA_CW 8
#define SKA_HW (SKA_H * SKA_W)

__global__ __launch_bounds__(128, 8)
void SKA_44830868635847_kernel(const float* __restrict__ x,
                               const float* __restrict__ wgt,
                               float* __restrict__ out) {
    const int tid  = threadIdx.x;
    const int lane = tid & 31;
    const int w0   = lane << 2;    // 0,4,...,124 (warp spans the full row)
    const int wid  = tid >> 5;     // 0..3
    const int h    = blockIdx.x;   // 0..127
    const int b    = blockIdx.y;   // 0..7

    const float* xb = x + (long)(b * SKA_C) * SKA_HW;
    float* ob = out + (long)(b * SKA_C) * SKA_HW;

    #pragma unroll 1
    for (int half = 0; half < 2; half++) {
        const int cw = wid + half * 4;   // weight channel for this pass

        // ---- L2 prefetch of this half's x rows (no registers consumed) ----
        // 8 channels x up-to-3 rows; one prefetch per 128B line (lane%8==0
        // lanes cover the row at 32-float granularity).
        if ((lane & 7) == 0) {
            #pragma unroll
            for (int g = 0; g < 8; g++) {
                const float* xc = xb + (long)((g * SKA_CW + cw) * SKA_HW);
                #pragma unroll
                for (int i = 0; i < 3; i++) {
                    const int hh = h + i - 1;
                    if (hh >= 0 && hh < SKA_H) {
                        const float* p = xc + hh * SKA_W + w0;
                        asm volatile("prefetch.global.L2 [%0];" :: "l"(p));
                    }
                }
            }
        }

        // 9 per-position weight vectors, in registers, reused across 8 channels.
        float4 wv[9];
        const float* wp = wgt + ((long)(b * SKA_CW + cw) * 9 * SKA_H + h) * SKA_W + w0;
        #pragma unroll
        for (int k = 0; k < 9; k++) {
            wv[k] = *reinterpret_cast<const float4*>(wp + (long)k * SKA_HW);
        }

        #pragma unroll
        for (int g = 0; g < 8; g++) {
            const int c = g * SKA_CW + cw;
            const float* xc = xb + (long)c * SKA_HW;

            float acc0 = 0.f, acc1 = 0.f, acc2 = 0.f, acc3 = 0.f;

            #pragma unroll
            for (int i = 0; i < 3; i++) {
                const int hh = h + i - 1;
                float r0, r1, r2, r3, r4, r5;
                if (hh < 0 || hh >= SKA_H) {           // warp-uniform
                    r0 = r1 = r2 = r3 = r4 = r5 = 0.f;
                } else {
                    const float* row = xc + hh * SKA_W + w0;
                    const float4 m = *reinterpret_cast<const float4*>(row);
                    r1 = m.x; r2 = m.y; r3 = m.z; r4 = m.w;
                    r0 = (w0 == 0)         ? 0.f : row[-1];
                    r5 = (w0 + 4 >= SKA_W) ? 0.f : row[4];
                }
                {
                    const float4 wk = wv[i * 3 + 0];   // j=0
                    acc0 = fmaf(wk.x, r0, acc0);
                    acc1 = fmaf(wk.y, r1, acc1);
                    acc2 = fmaf(wk.z, r2, acc2);
                    acc3 = fmaf(wk.w, r3, acc3);
                }
                {
                    const float4 wk = wv[i * 3 + 1];   // j=1
                    acc0 = fmaf(wk.x, r1, acc0);
                    acc1 = fmaf(wk.y, r2, acc1);
                    acc2 = fmaf(wk.z, r3, acc2);
                    acc3 = fmaf(wk.w, r4, acc3);
                }
                {
                    const float4 wk = wv[i * 3 + 2];   // j=2
                    acc0 = fmaf(wk.x, r2, acc0);
                    acc1 = fmaf(wk.y, r3, acc1);
                    acc2 = fmaf(wk.z, r4, acc2);
                    acc3 = fmaf(wk.w, r5, acc3);
                }
            }

            float4 o;
            o.x = acc0; o.y = acc1; o.z = acc2; o.w = acc3;
            *reinterpret_cast<float4*>(ob + (long)c * SKA_HW + h * SKA_W + w0) = o;
        }
    }
}

extern "C" void kernel_launch(void* const* d_in, const int* in_sizes, int n_in,
                              void* d_out, int out_size) {
    const float* x = (const float*)d_in[0];
    const float* w = (const float*)d_in[1];
    float* out = (float*)d_out;
    (void)in_sizes; (void)n_in; (void)out_size;

    dim3 grid(SKA_H, 8);   // (h, b): 1024 blocks
    dim3 block(128);       // 4 warps; each warp covers cw=wid and wid+4
    SKA_44830868635847_kernel<<<grid, block>>>(x, w, out);
}